// round 16
// baseline (speedup 1.0000x reference)
#include <cuda_runtime.h>
#include <cuda_fp16.h>
#include <cstdint>

// ---------------- problem constants ----------------
#define MM   8192
#define NN   2048
#define KIN  2048
#define KK   4096
#define NELEM_GRID ((double)KIN*NN*8)

// ---------------- GEMM: smem-free fragment-direct, persistent CTAs --------
#define BM 128
#define BN 128
#define NSLICE 256            // k16 slices
#define NI     512            // m16 tiles
#define NJP    128            // n16 tile-pairs (two n8 frags per slot)
#define NTILE  1024           // (MM/BM) * (NN/BN)
#define PGRID  304            // persistent grid
#define PFD    8              // A L2 prefetch distance (slices)

// A fragment slots: (S, I, lane) -> uint4  (a0,a1,a2,a3)
__device__ uint4 g_Af[(size_t)(NSLICE + 1) * NI * 32];   // +1 slice tail pad
// B fragment PAIR slots: (S, Jp, lane) -> uint4 (b0,b1 of J=2Jp | b0,b1 of J=2Jp+1)
__device__ uint4 g_Bf[(size_t)(NSLICE + 1) * NJP * 32];  // +1 slice tail pad
__device__ unsigned long long g_meanacc;   // fixed-point (2^-32) grid sum
__device__ unsigned int g_tile;            // persistent tile counter

// ---------------- helpers ----------------
__device__ __forceinline__ void mma_f16(float* d, const uint4& a, uint32_t b0, uint32_t b1) {
    asm volatile(
        "mma.sync.aligned.m16n8k16.row.col.f32.f16.f16.f32 "
        "{%0,%1,%2,%3}, {%4,%5,%6,%7}, {%8,%9}, {%0,%1,%2,%3};"
        : "+f"(d[0]), "+f"(d[1]), "+f"(d[2]), "+f"(d[3])
        : "r"(a.x), "r"(a.y), "r"(a.z), "r"(a.w), "r"(b0), "r"(b1));
}

__device__ __forceinline__ uint32_t pack_h2(float lo, float hi) {
    __half2 h = __floats2half2_rn(lo, hi);
    return *reinterpret_cast<uint32_t*>(&h);
}

__device__ __forceinline__ void pf_l2(const void* p) {
    asm volatile("prefetch.global.L2 [%0];" :: "l"(p));
}

// ======================= prep 1: grid reduce -> W2 B-fragments + mean =====
__global__ void k_gridsum(const float* __restrict__ grid) {
    __shared__ float tile[32][33];
    __shared__ float red[256];
    // reset persistent tile counter for the next k_gemm (stream-ordered)
    if (blockIdx.x == 0 && blockIdx.y == 0 && threadIdx.x == 0) g_tile = 0u;
    int i0 = blockIdx.x * 32, o0 = blockIdx.y * 32;
    int tx = threadIdx.x & 31, ty = threadIdx.x >> 5;   // 32 x 8
    const float4* g4 = reinterpret_cast<const float4*>(grid);
    float loc = 0.f;
    #pragma unroll
    for (int r = ty; r < 32; r += 8) {
        size_t idx8 = (size_t)(i0 + r) * NN + (o0 + tx);
        float4 p = g4[idx8 * 2];
        float4 q = g4[idx8 * 2 + 1];
        float s = ((p.x + p.y) + (p.z + p.w)) + ((q.x + q.y) + (q.z + q.w));
        tile[r][tx] = s;   // tile[i_local][o_local]
        loc += s;
    }
    red[threadIdx.x] = loc;
    __syncthreads();

    // write phase: 128 threads cover 2 S x 2 Jp x 32 lanes = 128 slots
    if (threadIdx.x < 128) {
        int t   = threadIdx.x;
        int sS  = t >> 6;            // 0..1
        int sJp = (t >> 5) & 1;      // 0..1
        int l   = t & 31;            // lane
        int n0_loc = sJp * 16 + (l >> 2);     // J = 2*(Jp) local n8 tile
        int n1_loc = n0_loc + 8;
        int i_loc  = sS * 16 + (l & 3) * 2;
        uint4 u;
        u.x = pack_h2(tile[i_loc][n0_loc],     tile[i_loc + 1][n0_loc]);
        u.y = pack_h2(tile[i_loc + 8][n0_loc], tile[i_loc + 9][n0_loc]);
        u.z = pack_h2(tile[i_loc][n1_loc],     tile[i_loc + 1][n1_loc]);
        u.w = pack_h2(tile[i_loc + 8][n1_loc], tile[i_loc + 9][n1_loc]);
        int S  = 128 + (i0 >> 4) + sS;
        int Jp = (o0 >> 4) + sJp;
        g_Bf[((size_t)S * NJP + Jp) * 32 + l] = u;
    }
    __syncthreads();

    for (int off = 128; off > 0; off >>= 1) {
        if (threadIdx.x < off) red[threadIdx.x] += red[threadIdx.x + off];
        __syncthreads();
    }
    if (threadIdx.x == 0) {
        long long q = llrint((double)red[0] * 4294967296.0);
        atomicAdd(&g_meanacc, (unsigned long long)q);
    }
}

// ======================= prep 2: Wb -> B-fragment pair slots (S<128) ======
__global__ void k_packWb(const float* __restrict__ bw) {
    int t = blockIdx.x * 256 + threadIdx.x;  // one pair-slot per thread, 512K
    int S  = t >> 12;            // 0..127
    int Jp = (t >> 5) & 127;     // 0..127
    int l  = t & 31;             // lane
    int n0 = Jp * 16 + (l >> 2);
    int n1 = n0 + 8;
    int k0 = S * 16 + (l & 3) * 2;
    const float2* bw2 = reinterpret_cast<const float2*>(bw);
    float2 a0 = bw2[(size_t)n0 * (KIN / 2) + (k0 >> 1)];
    float2 a1 = bw2[(size_t)n0 * (KIN / 2) + (k0 >> 1) + 4];
    float2 c0 = bw2[(size_t)n1 * (KIN / 2) + (k0 >> 1)];
    float2 c1 = bw2[(size_t)n1 * (KIN / 2) + (k0 >> 1) + 4];
    uint4 u;
    u.x = pack_h2(a0.x, a0.y);
    u.y = pack_h2(a1.x, a1.y);
    u.z = pack_h2(c0.x, c0.y);
    u.w = pack_h2(c1.x, c1.y);
    g_Bf[((size_t)S * NJP + Jp) * 32 + l] = u;
}

// ======= prep 3: x -> A-fragment slots [x half: S<128, basis: S>=128] =====
__global__ void k_buildA(const float* __restrict__ x) {
    int t = blockIdx.x * 256 + threadIdx.x;
    int l  = t & 31;             // lane
    int I  = (t >> 5) & 511;     // m16 tile
    int S  = t >> 14;            // 0..127 (k16 slice within x half)
    int m  = I * 16 + (l >> 2);
    int k0 = S * 16 + (l & 3) * 2;
    const float2* x2 = reinterpret_cast<const float2*>(x);
    float2 f0 = x2[(size_t)m * (KIN / 2) + (k0 >> 1)];
    float2 f1 = x2[(size_t)(m + 8) * (KIN / 2) + (k0 >> 1)];
    float2 f2 = x2[(size_t)m * (KIN / 2) + (k0 >> 1) + 4];
    float2 f3 = x2[(size_t)(m + 8) * (KIN / 2) + (k0 >> 1) + 4];

    uint4 ux;
    ux.x = pack_h2(f0.x, f0.y);
    ux.y = pack_h2(f1.x, f1.y);
    ux.z = pack_h2(f2.x, f2.y);
    ux.w = pack_h2(f3.x, f3.y);
    g_Af[((size_t)S * NI + I) * 32 + l] = ux;

    double acc = (double)(long long)g_meanacc;
    float mn = (float)(acc * (1.0 / 4294967296.0) / NELEM_GRID);
    float d0 = f0.x - mn, d1 = f0.y - mn, d2 = f1.x - mn, d3 = f1.y - mn;
    float d4 = f2.x - mn, d5 = f2.y - mn, d6 = f3.x - mn, d7 = f3.y - mn;
    uint4 ub;
    ub.x = pack_h2(__expf(-d0 * d0), __expf(-d1 * d1));
    ub.y = pack_h2(__expf(-d2 * d2), __expf(-d3 * d3));
    ub.z = pack_h2(__expf(-d4 * d4), __expf(-d5 * d5));
    ub.w = pack_h2(__expf(-d6 * d6), __expf(-d7 * d7));
    g_Af[((size_t)(S + 128) * NI + I) * 32 + l] = ub;
}

// == main GEMM: persistent, smem-free, paired-B fragment-direct ============
__global__ __launch_bounds__(256, 2) void k_gemm(float* __restrict__ out) {
    // reset mean accumulator for the next graph replay
    if (blockIdx.x == 0 && threadIdx.x == 0) g_meanacc = 0ULL;

    __shared__ unsigned int s_tile;
    int tid  = threadIdx.x;
    int warp = tid >> 5, lane = tid & 31;
    int wm = warp & 3;         // 4 warps along M -> 32 rows each
    int wn = warp >> 2;        // 2 warps along N -> 64 cols each
    int g  = lane >> 2;        // 0..7
    int tg = lane & 3;         // 0..3

    for (;;) {
        if (tid == 0) s_tile = atomicAdd(&g_tile, 1u);
        __syncthreads();
        unsigned int t = s_tile;
        __syncthreads();              // protect s_tile before next overwrite
        if (t >= NTILE) break;

        int n0 = (int)(t & 15) * BN;
        int m0 = (int)(t >> 4) * BM;

        const uint4* Ap = g_Af + ((size_t)((m0 >> 4) + wm * 2)) * 32 + lane;
        const uint4* Bp = g_Bf + ((size_t)((n0 >> 4) + wn * 4)) * 32 + lane;

        float acc[2][8][4];
        #pragma unroll
        for (int i = 0; i < 2; i++)
            #pragma unroll
            for (int j = 0; j < 8; j++)
                #pragma unroll
                for (int k = 0; k < 4; k++) acc[i][j][k] = 0.f;

        // prologue: slice 0 fragments
        uint4 areg[2][2];
        uint4 breg[2][4];
        #pragma unroll
        for (int mf = 0; mf < 2; ++mf)
            areg[0][mf] = __ldg(Ap + mf * 32);
        #pragma unroll
        for (int f4 = 0; f4 < 4; ++f4)
            breg[0][f4] = __ldg(Bp + f4 * 32);

        #pragma unroll 4
        for (int S = 0; S < NSLICE; ++S) {
            int par = S & 1;
            // L2 prefetch of A PFD slices ahead (clamped into the pad slice)
            int Spf = S + PFD; if (Spf > NSLICE) Spf = NSLICE;
            size_t offPF = (size_t)Spf * (NI * 32);
            pf_l2(Ap + offPF);
            pf_l2(Ap + offPF + 32);

            // prefetch next slice's fragments into registers
            size_t offA = (size_t)(S + 1) * (NI * 32);
            size_t offB = (size_t)(S + 1) * (NJP * 32);
            #pragma unroll
            for (int mf = 0; mf < 2; ++mf)
                areg[par ^ 1][mf] = __ldg(Ap + offA + mf * 32);
            #pragma unroll
            for (int f4 = 0; f4 < 4; ++f4)
                breg[par ^ 1][f4] = __ldg(Bp + offB + f4 * 32);

            #pragma unroll
            for (int f4 = 0; f4 < 4; ++f4) {
                uint4 bb = breg[par][f4];
                #pragma unroll
                for (int mf = 0; mf < 2; ++mf) {
                    mma_f16(acc[mf][f4 * 2 + 0], areg[par][mf], bb.x, bb.y);
                    mma_f16(acc[mf][f4 * 2 + 1], areg[par][mf], bb.z, bb.w);
                }
            }
        }

        // epilogue (warp-private output tile)
        #pragma unroll
        for (int mf = 0; mf < 2; ++mf) {
            #pragma unroll
            for (int nf = 0; nf < 8; ++nf) {
                int row0 = m0 + wm * 32 + mf * 16 + g;
                int col  = n0 + wn * 64 + nf * 8 + tg * 2;
                float2 v0 = make_float2(acc[mf][nf][0], acc[mf][nf][1]);
                float2 v1 = make_float2(acc[mf][nf][2], acc[mf][nf][3]);
                *reinterpret_cast<float2*>(&out[(size_t)row0 * NN + col])       = v0;
                *reinterpret_cast<float2*>(&out[(size_t)(row0 + 8) * NN + col]) = v1;
            }
        }
    }
}

// ============================= launch =====================================
extern "C" void kernel_launch(void* const* d_in, const int* in_sizes, int n_in,
                              void* d_out, int out_size) {
    const float* x    = (const float*)d_in[0];   // (8192, 2048)
    const float* bw   = (const float*)d_in[1];   // (2048, 2048)
    const float* grid = (const float*)d_in[2];   // (2048, 2048, 8)
    float* out = (float*)d_out;                  // (8192, 2048)

    k_gridsum<<<dim3(KIN / 32, NN / 32), 256>>>(grid);
    k_packWb<<<(128 * 128 * 32) / 256, 256>>>(bw);
    k_buildA<<<(128 * 512 * 32) / 256, 256>>>(x);
    k_gemm<<<PGRID, 256>>>(out);
}

// round 17
// speedup vs baseline: 1.0625x; 1.0625x over previous
#include <cuda_runtime.h>
#include <cuda_fp16.h>
#include <cstdint>

// ---------------- problem constants ----------------
#define MM   8192
#define NN   2048
#define KIN  2048
#define KK   4096
#define NELEM_GRID ((double)KIN*NN*8)

// ---------------- GEMM: smem-free fragment-direct, persistent CTAs --------
#define BM 128
#define BN 128
#define NSLICE 256            // k16 slices
#define NI     512            // m16 tiles
#define NJ     256            // n8 tiles
#define NTILE  1024           // (MM/BM) * (NN/BN)
#define PGRID  304            // persistent grid
#define PFD    16             // A L2 prefetch distance (slices)

// A fragment slots: (S, I, lane) -> uint4  (a0,a1,a2,a3)
__device__ uint4 g_Af[(size_t)(NSLICE + PFD) * NI * 32];   // tail pad for pf
// B fragment slots: (S, J, lane) -> uint2  (b0,b1)
__device__ uint2 g_Bf[(size_t)(NSLICE + 1) * NJ * 32];     // +1 slice tail pad
__device__ unsigned long long g_meanacc;   // fixed-point (2^-32) grid sum
__device__ unsigned int g_tile;            // persistent tile counter

// ---------------- helpers ----------------
__device__ __forceinline__ void mma_f16(float* d, const uint4& a, uint32_t b0, uint32_t b1) {
    asm volatile(
        "mma.sync.aligned.m16n8k16.row.col.f32.f16.f16.f32 "
        "{%0,%1,%2,%3}, {%4,%5,%6,%7}, {%8,%9}, {%0,%1,%2,%3};"
        : "+f"(d[0]), "+f"(d[1]), "+f"(d[2]), "+f"(d[3])
        : "r"(a.x), "r"(a.y), "r"(a.z), "r"(a.w), "r"(b0), "r"(b1));
}

__device__ __forceinline__ uint32_t pack_h2(float lo, float hi) {
    __half2 h = __floats2half2_rn(lo, hi);
    return *reinterpret_cast<uint32_t*>(&h);
}

__device__ __forceinline__ void pf_l2(const void* p) {
    asm volatile("prefetch.global.L2 [%0];" :: "l"(p));
}

// ======================= prep 1: grid reduce -> W2 B-fragments + mean =====
__global__ void k_gridsum(const float* __restrict__ grid) {
    __shared__ float tile[32][33];
    __shared__ float red[256];
    // reset persistent tile counter for the next k_gemm (stream-ordered)
    if (blockIdx.x == 0 && blockIdx.y == 0 && threadIdx.x == 0) g_tile = 0u;
    int i0 = blockIdx.x * 32, o0 = blockIdx.y * 32;
    int tx = threadIdx.x & 31, ty = threadIdx.x >> 5;   // 32 x 8
    const float4* g4 = reinterpret_cast<const float4*>(grid);
    float loc = 0.f;
    #pragma unroll
    for (int r = ty; r < 32; r += 8) {
        size_t idx8 = (size_t)(i0 + r) * NN + (o0 + tx);
        float4 p = g4[idx8 * 2];
        float4 q = g4[idx8 * 2 + 1];
        float s = ((p.x + p.y) + (p.z + p.w)) + ((q.x + q.y) + (q.z + q.w));
        tile[r][tx] = s;   // tile[i_local][o_local]
        loc += s;
    }
    red[threadIdx.x] = loc;
    __syncthreads();

    // write phase: 256 threads cover 2 S x 4 J x 32 lanes = 256 slots
    {
        int t  = threadIdx.x;
        int sS = t >> 7;            // 0..1
        int sJ = (t >> 5) & 3;      // 0..3
        int l  = t & 31;            // lane
        int o_loc = sJ * 8 + (l >> 2);
        int i_loc = sS * 16 + (l & 3) * 2;
        uint2 u;
        u.x = pack_h2(tile[i_loc][o_loc],     tile[i_loc + 1][o_loc]);
        u.y = pack_h2(tile[i_loc + 8][o_loc], tile[i_loc + 9][o_loc]);
        int S = 128 + (i0 >> 4) + sS;
        int J = (o0 >> 3) + sJ;
        g_Bf[((size_t)S * NJ + J) * 32 + l] = u;
    }

    for (int off = 128; off > 0; off >>= 1) {
        if (threadIdx.x < off) red[threadIdx.x] += red[threadIdx.x + off];
        __syncthreads();
    }
    if (threadIdx.x == 0) {
        long long q = llrint((double)red[0] * 4294967296.0);
        atomicAdd(&g_meanacc, (unsigned long long)q);
    }
}

// ======================= prep 2: Wb -> B-fragment slots (S in [0,128)) ====
__global__ void k_packWb(const float* __restrict__ bw) {
    int t = blockIdx.x * 256 + threadIdx.x;  // one slot per thread, 1M total
    int S = t >> 13;            // 0..127
    int J = (t >> 5) & 255;     // 0..255
    int l = t & 31;             // lane
    int n  = J * 8 + (l >> 2);
    int k0 = S * 16 + (l & 3) * 2;
    const float2* bw2 = reinterpret_cast<const float2*>(bw);
    float2 a = bw2[(size_t)n * (KIN / 2) + (k0 >> 1)];
    float2 b = bw2[(size_t)n * (KIN / 2) + (k0 >> 1) + 4];
    uint2 u;
    u.x = pack_h2(a.x, a.y);
    u.y = pack_h2(b.x, b.y);
    g_Bf[((size_t)S * NJ + J) * 32 + l] = u;
}

// ======= prep 3: x -> A-fragment slots [x half: S<128, basis: S>=128] =====
__global__ void k_buildA(const float* __restrict__ x) {
    int t = blockIdx.x * 256 + threadIdx.x;
    int l  = t & 31;             // lane
    int I  = (t >> 5) & 511;     // m16 tile
    int S  = t >> 14;            // 0..127 (k16 slice within x half)
    int m  = I * 16 + (l >> 2);
    int k0 = S * 16 + (l & 3) * 2;
    const float2* x2 = reinterpret_cast<const float2*>(x);
    float2 f0 = x2[(size_t)m * (KIN / 2) + (k0 >> 1)];
    float2 f1 = x2[(size_t)(m + 8) * (KIN / 2) + (k0 >> 1)];
    float2 f2 = x2[(size_t)m * (KIN / 2) + (k0 >> 1) + 4];
    float2 f3 = x2[(size_t)(m + 8) * (KIN / 2) + (k0 >> 1) + 4];

    uint4 ux;
    ux.x = pack_h2(f0.x, f0.y);
    ux.y = pack_h2(f1.x, f1.y);
    ux.z = pack_h2(f2.x, f2.y);
    ux.w = pack_h2(f3.x, f3.y);
    g_Af[((size_t)S * NI + I) * 32 + l] = ux;

    double acc = (double)(long long)g_meanacc;
    float mn = (float)(acc * (1.0 / 4294967296.0) / NELEM_GRID);
    float d0 = f0.x - mn, d1 = f0.y - mn, d2 = f1.x - mn, d3 = f1.y - mn;
    float d4 = f2.x - mn, d5 = f2.y - mn, d6 = f3.x - mn, d7 = f3.y - mn;
    uint4 ub;
    ub.x = pack_h2(__expf(-d0 * d0), __expf(-d1 * d1));
    ub.y = pack_h2(__expf(-d2 * d2), __expf(-d3 * d3));
    ub.z = pack_h2(__expf(-d4 * d4), __expf(-d5 * d5));
    ub.w = pack_h2(__expf(-d6 * d6), __expf(-d7 * d7));
    g_Af[((size_t)(S + 128) * NI + I) * 32 + l] = ub;
}

// == main GEMM: persistent, smem-free, fragment-direct, L2-prefetched ======
__global__ __launch_bounds__(256, 2) void k_gemm(float* __restrict__ out) {
    // reset mean accumulator for the next graph replay
    if (blockIdx.x == 0 && threadIdx.x == 0) g_meanacc = 0ULL;

    __shared__ unsigned int s_tile;
    int tid  = threadIdx.x;
    int warp = tid >> 5, lane = tid & 31;
    int wm = warp & 3;         // 4 warps along M -> 32 rows each
    int wn = warp >> 2;        // 2 warps along N -> 64 cols each
    int g  = lane >> 2;        // 0..7
    int tg = lane & 3;         // 0..3

    for (;;) {
        if (tid == 0) s_tile = atomicAdd(&g_tile, 1u);
        __syncthreads();
        unsigned int t = s_tile;
        __syncthreads();              // protect s_tile before next overwrite
        if (t >= NTILE) break;

        int n0 = (int)(t & 15) * BN;
        int m0 = (int)(t >> 4) * BM;

        const uint4* Ap = g_Af + ((size_t)((m0 >> 4) + wm * 2)) * 32 + lane;
        const uint2* Bp = g_Bf + ((size_t)((n0 >> 3) + wn * 8)) * 32 + lane;

        float acc[2][8][4];
        #pragma unroll
        for (int i = 0; i < 2; i++)
            #pragma unroll
            for (int j = 0; j < 8; j++)
                #pragma unroll
                for (int k = 0; k < 4; k++) acc[i][j][k] = 0.f;

        // prologue: slice 0 fragments (B first: it feeds 8 of 10 consumers)
        uint4 areg[2][2];
        uint2 breg[2][8];
        #pragma unroll
        for (int f = 0; f < 8; ++f)
            breg[0][f] = __ldg(Bp + f * 32);
        #pragma unroll
        for (int mf = 0; mf < 2; ++mf)
            areg[0][mf] = __ldg(Ap + mf * 32);

        #pragma unroll 8
        for (int S = 0; S < NSLICE; ++S) {
            int par = S & 1;
            // L2 prefetch of A PFD slices ahead (pad region absorbs the tail)
            size_t offPF = (size_t)(S + PFD) * (NI * 32);
            pf_l2(Ap + offPF);
            pf_l2(Ap + offPF + 32);

            // prefetch next slice's fragments into registers (B first)
            size_t offA = (size_t)(S + 1) * (NI * 32);
            size_t offB = (size_t)(S + 1) * (NJ * 32);
            #pragma unroll
            for (int f = 0; f < 8; ++f)
                breg[par ^ 1][f] = __ldg(Bp + offB + f * 32);
            #pragma unroll
            for (int mf = 0; mf < 2; ++mf)
                areg[par ^ 1][mf] = __ldg(Ap + offA + mf * 32);

            #pragma unroll
            for (int f = 0; f < 8; ++f) {
                uint2 bb = breg[par][f];
                #pragma unroll
                for (int mf = 0; mf < 2; ++mf)
                    mma_f16(acc[mf][f], areg[par][mf], bb.x, bb.y);
            }
        }

        // epilogue (warp-private output tile)
        #pragma unroll
        for (int mf = 0; mf < 2; ++mf) {
            #pragma unroll
            for (int nf = 0; nf < 8; ++nf) {
                int row0 = m0 + wm * 32 + mf * 16 + g;
                int col  = n0 + wn * 64 + nf * 8 + tg * 2;
                float2 v0 = make_float2(acc[mf][nf][0], acc[mf][nf][1]);
                float2 v1 = make_float2(acc[mf][nf][2], acc[mf][nf][3]);
                *reinterpret_cast<float2*>(&out[(size_t)row0 * NN + col])       = v0;
                *reinterpret_cast<float2*>(&out[(size_t)(row0 + 8) * NN + col]) = v1;
            }
        }
    }
}

// ============================= launch =====================================
extern "C" void kernel_launch(void* const* d_in, const int* in_sizes, int n_in,
                              void* d_out, int out_size) {
    const float* x    = (const float*)d_in[0];   // (8192, 2048)
    const float* bw   = (const float*)d_in[1];   // (2048, 2048)
    const float* grid = (const float*)d_in[2];   // (2048, 2048, 8)
    float* out = (float*)d_out;                  // (8192, 2048)

    k_gridsum<<<dim3(KIN / 32, NN / 32), 256>>>(grid);
    k_packWb<<<(128 * 256 * 32) / 256, 256>>>(bw);
    k_buildA<<<(128 * 512 * 32) / 256, 256>>>(x);
    k_gemm<<<PGRID, 256>>>(out);
}